// round 17
// baseline (speedup 1.0000x reference)
#include <cuda_runtime.h>
#include <math.h>
#include <stdint.h>

#define NN 50000
#define EE 800000
#define GG 64
#define NBLK 196          // ceil(NN/256)
#define GMB1 391          // gemm1 blocks: ceil(NN/128)
#define HB1 391           // hist blocks: ceil(EE/2048)
#define GMB2 391          // gemm2 blocks: ceil(NN/128)
#define EDGEB 6250        // NN*32/256
#define SCB 782           // csr blocks: ceil(EE/1024)

// ---------------- scratch (zero-init at load; self-cleaning per call) -------
__device__ float g_h1[NN * 128];
__device__ float g_hrelu[NN * 128];
__device__ float g_h2[NN * 64];
__device__ float g_asrc1[NN * 4];
__device__ float g_adst1[NN * 4];
__device__ float g_asrc2[NN];
__device__ float g_adst2[NN];
__device__ int   g_cnt[NN];        // zeroed inside k_csr after use
__device__ int   g_cur[NN];
__device__ int   g_off[NN + 1];
__device__ int   g_bsum[NBLK];
__device__ int2  g_sep[EE];        // packed (src, edge_attr bits), permuted
__device__ float g_ce1[4];
__device__ float g_ce2v[1];
__device__ float g_gsum[GG * 64];  // zeroed by k_final after use
__device__ float g_gcnt[GG];       // zeroed by k_final after use
__device__ unsigned g_barc;        // grid-barrier counter; self-resets

__device__ __forceinline__ uint32_t f2tf32(float x) {
    uint32_t u;
    asm("cvt.rna.tf32.f32 %0, %1;" : "=r"(u) : "f"(x));
    return u;
}

__device__ __forceinline__ void mma_tf32(float c[4], const uint32_t a[4],
                                         const uint32_t b[2]) {
    asm volatile(
        "mma.sync.aligned.m16n8k8.row.col.f32.tf32.tf32.f32 "
        "{%0,%1,%2,%3}, {%4,%5,%6,%7}, {%8,%9}, {%0,%1,%2,%3};"
        : "+f"(c[0]), "+f"(c[1]), "+f"(c[2]), "+f"(c[3])
        : "r"(a[0]), "r"(a[1]), "r"(a[2]), "r"(a[3]), "r"(b[0]), "r"(b[1]));
}

// grid barrier: all SCB blocks are wave-1 co-resident (6256 warps < 9472 slots)
__device__ __forceinline__ void gridbar(unsigned target) {
    __syncthreads();
    if (threadIdx.x == 0) {
        __threadfence();
        atomicAdd(&g_barc, 1u);
        while (*((volatile unsigned*)&g_barc) < target) __nanosleep(64);
    }
    __syncthreads();
}

// ======== K1: tf32 MMA GEMM1 (+att1 epilogue), fused hist + ce constants ====
__global__ __launch_bounds__(256, 2)
void k_l1(const float* __restrict__ A, const float* __restrict__ B,
          const float* __restrict__ as1, const float* __restrict__ ad1,
          const int* __restrict__ dst,
          const float* __restrict__ We1, const float* __restrict__ ae1,
          const float* __restrict__ We2, const float* __restrict__ ae2) {
    __shared__ uint32_t As[128 * 36];
    __shared__ uint32_t Bs[32 * 136];

    int tid = threadIdx.x;
    if (blockIdx.x >= GMB1) {
        int hb = blockIdx.x - GMB1;
        if (hb == 0 && tid < 8) {
            int h = tid;
            if (h < 4) {
                float s = 0.f;
                for (int c = 0; c < 32; c++) s += We1[h * 32 + c] * ae1[h * 32 + c];
                g_ce1[h] = s;
            } else if (h == 4) {
                float s = 0.f;
                for (int c = 0; c < 64; c++) s += We2[c] * ae2[c];
                g_ce2v[0] = s;
            }
        }
        int base = hb * 2048 + tid;
#pragma unroll
        for (int i = 0; i < 8; i++) {
            int e = base + i * 256;
            if (e < EE) atomicAdd(&g_cnt[dst[e]], 1);
        }
        return;
    }

    int wid = tid >> 5;
    int lane = tid & 31;
    int wm = wid & 3;
    int wn = wid >> 2;
    int g = lane >> 2;
    int q = lane & 3;
    int row0 = blockIdx.x * 128;

    float acc[2][8][4];
#pragma unroll
    for (int mt = 0; mt < 2; mt++)
#pragma unroll
        for (int nf = 0; nf < 8; nf++)
#pragma unroll
            for (int r = 0; r < 4; r++) acc[mt][nf][r] = 0.f;

    for (int kt = 0; kt < 128; kt += 32) {
#pragma unroll
        for (int i = 0; i < 4; i++) {
            int f = tid + i * 256;
            int r = f >> 3, kc = (f & 7) * 4;
            float4 v = (row0 + r < NN)
                ? *reinterpret_cast<const float4*>(&A[(row0 + r) * 128 + kt + kc])
                : make_float4(0.f, 0.f, 0.f, 0.f);
            uint32_t* p = &As[r * 36 + kc];
            p[0] = f2tf32(v.x); p[1] = f2tf32(v.y);
            p[2] = f2tf32(v.z); p[3] = f2tf32(v.w);
        }
#pragma unroll
        for (int i = 0; i < 4; i++) {
            int f = tid + i * 256;
            int r = f >> 5, c = (f & 31) * 4;
            float4 v = *reinterpret_cast<const float4*>(&B[(kt + r) * 128 + c]);
            uint32_t* p = &Bs[r * 136 + c];
            p[0] = f2tf32(v.x); p[1] = f2tf32(v.y);
            p[2] = f2tf32(v.z); p[3] = f2tf32(v.w);
        }
        __syncthreads();

#pragma unroll
        for (int ks = 0; ks < 32; ks += 8) {
            uint32_t a[2][4];
#pragma unroll
            for (int mt = 0; mt < 2; mt++) {
                int r = wm * 32 + mt * 16 + g;
                a[mt][0] = As[r * 36 + ks + q];
                a[mt][1] = As[(r + 8) * 36 + ks + q];
                a[mt][2] = As[r * 36 + ks + q + 4];
                a[mt][3] = As[(r + 8) * 36 + ks + q + 4];
            }
            uint32_t b[8][2];
#pragma unroll
            for (int nf = 0; nf < 8; nf++) {
                int c = wn * 64 + nf * 8 + g;
                b[nf][0] = Bs[(ks + q) * 136 + c];
                b[nf][1] = Bs[(ks + q + 4) * 136 + c];
            }
#pragma unroll
            for (int mt = 0; mt < 2; mt++)
#pragma unroll
                for (int nf = 0; nf < 8; nf++) mma_tf32(acc[mt][nf], a[mt], b[nf]);
        }
        __syncthreads();
    }

#pragma unroll
    for (int mt = 0; mt < 2; mt++) {
        int rlo = row0 + wm * 32 + mt * 16 + g;
        int rhi = rlo + 8;
        float psl[2] = {0.f, 0.f}, pdl2[2] = {0.f, 0.f};
        float psh[2] = {0.f, 0.f}, pdh[2] = {0.f, 0.f};
#pragma unroll
        for (int nf = 0; nf < 8; nf++) {
            int col = wn * 64 + nf * 8 + 2 * q;
            float s0 = as1[col], s1 = as1[col + 1];
            float d0 = ad1[col], d1 = ad1[col + 1];
            int hh = nf >> 2;
            psl[hh] += acc[mt][nf][0] * s0 + acc[mt][nf][1] * s1;
            pdl2[hh] += acc[mt][nf][0] * d0 + acc[mt][nf][1] * d1;
            psh[hh] += acc[mt][nf][2] * s0 + acc[mt][nf][3] * s1;
            pdh[hh] += acc[mt][nf][2] * d0 + acc[mt][nf][3] * d1;
        }
#pragma unroll
        for (int off = 1; off < 4; off <<= 1) {
#pragma unroll
            for (int hh = 0; hh < 2; hh++) {
                psl[hh] += __shfl_xor_sync(0xffffffffu, psl[hh], off);
                pdl2[hh] += __shfl_xor_sync(0xffffffffu, pdl2[hh], off);
                psh[hh] += __shfl_xor_sync(0xffffffffu, psh[hh], off);
                pdh[hh] += __shfl_xor_sync(0xffffffffu, pdh[hh], off);
            }
        }
        if (rlo < NN) {
#pragma unroll
            for (int nf = 0; nf < 8; nf++) {
                float2 v = make_float2(acc[mt][nf][0], acc[mt][nf][1]);
                *reinterpret_cast<float2*>(&g_h1[rlo * 128 + wn * 64 + nf * 8 + 2 * q]) = v;
            }
            if (q == 0) {
                g_asrc1[rlo * 4 + 2 * wn]     = psl[0];
                g_asrc1[rlo * 4 + 2 * wn + 1] = psl[1];
                g_adst1[rlo * 4 + 2 * wn]     = pdl2[0];
                g_adst1[rlo * 4 + 2 * wn + 1] = pdl2[1];
            }
        }
        if (rhi < NN) {
#pragma unroll
            for (int nf = 0; nf < 8; nf++) {
                float2 v = make_float2(acc[mt][nf][2], acc[mt][nf][3]);
                *reinterpret_cast<float2*>(&g_h1[rhi * 128 + wn * 64 + nf * 8 + 2 * q]) = v;
            }
            if (q == 0) {
                g_asrc1[rhi * 4 + 2 * wn]     = psh[0];
                g_asrc1[rhi * 4 + 2 * wn + 1] = psh[1];
                g_adst1[rhi * 4 + 2 * wn]     = pdh[0];
                g_adst1[rhi * 4 + 2 * wn + 1] = pdh[1];
            }
        }
    }
}

// ======== GEMM2: tf32 MMA, CTA 128x64, 8 warps (8m x 1n, 16 rows each) ======
__global__ __launch_bounds__(256, 3)
void k_l2(const float* __restrict__ W2,
          const float* __restrict__ as2, const float* __restrict__ ad2) {
    __shared__ uint32_t As[128 * 36];
    __shared__ uint32_t Bs[32 * 72];

    int tid = threadIdx.x;
    int wid = tid >> 5;
    int lane = tid & 31;
    int g = lane >> 2;
    int q = lane & 3;
    int row0 = blockIdx.x * 128;

    float acc[8][4];
#pragma unroll
    for (int nf = 0; nf < 8; nf++)
#pragma unroll
        for (int r = 0; r < 4; r++) acc[nf][r] = 0.f;

    for (int kt = 0; kt < 128; kt += 32) {
#pragma unroll
        for (int i = 0; i < 4; i++) {
            int f = tid + i * 256;
            int r = f >> 3, kc = (f & 7) * 4;
            float4 v = (row0 + r < NN)
                ? *reinterpret_cast<const float4*>(&g_hrelu[(row0 + r) * 128 + kt + kc])
                : make_float4(0.f, 0.f, 0.f, 0.f);
            uint32_t* p = &As[r * 36 + kc];
            p[0] = f2tf32(v.x); p[1] = f2tf32(v.y);
            p[2] = f2tf32(v.z); p[3] = f2tf32(v.w);
        }
#pragma unroll
        for (int i = 0; i < 2; i++) {
            int f = tid + i * 256;
            int r = f >> 4, c = (f & 15) * 4;
            float4 v = *reinterpret_cast<const float4*>(&W2[(kt + r) * 64 + c]);
            uint32_t* p = &Bs[r * 72 + c];
            p[0] = f2tf32(v.x); p[1] = f2tf32(v.y);
            p[2] = f2tf32(v.z); p[3] = f2tf32(v.w);
        }
        __syncthreads();

#pragma unroll
        for (int ks = 0; ks < 32; ks += 8) {
            uint32_t a[4];
            int r = wid * 16 + g;
            a[0] = As[r * 36 + ks + q];
            a[1] = As[(r + 8) * 36 + ks + q];
            a[2] = As[r * 36 + ks + q + 4];
            a[3] = As[(r + 8) * 36 + ks + q + 4];
            uint32_t b[8][2];
#pragma unroll
            for (int nf = 0; nf < 8; nf++) {
                int c = nf * 8 + g;
                b[nf][0] = Bs[(ks + q) * 72 + c];
                b[nf][1] = Bs[(ks + q + 4) * 72 + c];
            }
#pragma unroll
            for (int nf = 0; nf < 8; nf++) mma_tf32(acc[nf], a, b[nf]);
        }
        __syncthreads();
    }

    int rlo = row0 + wid * 16 + g;
    int rhi = rlo + 8;
    float psl = 0.f, pdl2 = 0.f, psh = 0.f, pdh = 0.f;
#pragma unroll
    for (int nf = 0; nf < 8; nf++) {
        int col = nf * 8 + 2 * q;
        float s0 = as2[col], s1 = as2[col + 1];
        float d0 = ad2[col], d1 = ad2[col + 1];
        psl += acc[nf][0] * s0 + acc[nf][1] * s1;
        pdl2 += acc[nf][0] * d0 + acc[nf][1] * d1;
        psh += acc[nf][2] * s0 + acc[nf][3] * s1;
        pdh += acc[nf][2] * d0 + acc[nf][3] * d1;
    }
#pragma unroll
    for (int off = 1; off < 4; off <<= 1) {
        psl += __shfl_xor_sync(0xffffffffu, psl, off);
        pdl2 += __shfl_xor_sync(0xffffffffu, pdl2, off);
        psh += __shfl_xor_sync(0xffffffffu, psh, off);
        pdh += __shfl_xor_sync(0xffffffffu, pdh, off);
    }
    if (rlo < NN) {
#pragma unroll
        for (int nf = 0; nf < 8; nf++) {
            float2 v = make_float2(acc[nf][0], acc[nf][1]);
            *reinterpret_cast<float2*>(&g_h2[rlo * 64 + nf * 8 + 2 * q]) = v;
        }
        if (q == 0) { g_asrc2[rlo] = psl; g_adst2[rlo] = pdl2; }
    }
    if (rhi < NN) {
#pragma unroll
        for (int nf = 0; nf < 8; nf++) {
            float2 v = make_float2(acc[nf][2], acc[nf][3]);
            *reinterpret_cast<float2*>(&g_h2[rhi * 64 + nf * 8 + 2 * q]) = v;
        }
        if (q == 0) { g_asrc2[rhi] = psh; g_adst2[rhi] = pdh; }
    }
}

// ======== fused CSR: bsum -> barrier -> off -> barrier -> scatter ==========
__global__ __launch_bounds__(256)
void k_csr(const int* __restrict__ src, const int* __restrict__ dst,
           const float* __restrict__ eattr) {
    __shared__ int s[256];
    __shared__ int bs[256];
    int bid = blockIdx.x;
    int t = threadIdx.x;

    if (bid < NBLK) {
        int idx = bid * 256 + t;
        s[t] = (idx < NN) ? g_cnt[idx] : 0;
        __syncthreads();
        for (int off = 128; off; off >>= 1) {
            if (t < off) s[t] += s[t + off];
            __syncthreads();
        }
        if (t == 0) g_bsum[bid] = s[0];
    }
    gridbar(SCB);

    if (bid < NBLK) {
        bs[t] = (t < NBLK) ? g_bsum[t] : 0;
        __syncthreads();
        for (int off = 1; off < 256; off <<= 1) {
            int v = (t >= off) ? bs[t - off] : 0;
            __syncthreads();
            bs[t] += v;
            __syncthreads();
        }
        int blockBase = (bid == 0) ? 0 : bs[bid - 1];

        int idx = bid * 256 + t;
        int val = (idx < NN) ? g_cnt[idx] : 0;
        s[t] = val;
        __syncthreads();
        for (int off = 1; off < 256; off <<= 1) {
            int v = (t >= off) ? s[t - off] : 0;
            __syncthreads();
            s[t] += v;
            __syncthreads();
        }
        int excl = blockBase + s[t] - val;
        if (idx <= NN) {
            g_off[idx] = excl;
            if (idx < NN) {
                g_cur[idx] = excl;
                g_cnt[idx] = 0;     // self-clean for next call
            }
        }
    }
    gridbar(2u * SCB);

    {
        int base = bid * 1024 + t;
        int sv[4], d[4];
        float ea[4];
        bool ok[4];
#pragma unroll
        for (int i = 0; i < 4; i++) {
            int e = base + i * 256;
            ok[i] = (e < EE);
            if (ok[i]) { sv[i] = src[e]; d[i] = dst[e]; ea[i] = eattr[e]; }
        }
#pragma unroll
        for (int i = 0; i < 4; i++) {
            if (ok[i]) {
                int pos = atomicAdd(&g_cur[d[i]], 1);
                g_sep[pos] = make_int2(sv[i], __float_as_int(ea[i]));
            }
        }
    }

    __syncthreads();
    if (t == 0) {
        unsigned v = atomicAdd(&g_barc, 1u);
        if (v == 3u * SCB - 1u) g_barc = 0;   // self-reset for graph replay
    }
}

// ---------------- warp-per-node aggregation, layer 1 -------------------------
__global__ __launch_bounds__(256, 8)
void k_edge1(const float* __restrict__ b1) {
    int w = (blockIdx.x * blockDim.x + threadIdx.x) >> 5;
    if (w >= NN) return;
    int lane = threadIdx.x & 31;
    int hh = lane >> 3;
    float4 bv = *reinterpret_cast<const float4*>(&b1[lane * 4]);
    int beg = g_off[w], end = g_off[w + 1];
    float4 o;
    if (beg == end) {
        o.x = fmaxf(bv.x, 0.f); o.y = fmaxf(bv.y, 0.f);
        o.z = fmaxf(bv.z, 0.f); o.w = fmaxf(bv.w, 0.f);
    } else {
        float adw = g_adst1[w * 4 + hh];
        float ceh = g_ce1[hh];
        float ax = 0.f, ay = 0.f, az = 0.f, aw = 0.f, den = 0.f;
#pragma unroll 8
        for (int j = beg; j < end; j++) {
            int2 p = g_sep[j];
            int s = p.x;
            float v = g_asrc1[s * 4 + hh] + adw + __int_as_float(p.y) * ceh;
            v = v > 0.f ? v : 0.2f * v;
            float e = __expf(v);
            den += e;
            float4 hv = *reinterpret_cast<const float4*>(&g_h1[s * 128 + lane * 4]);
            ax = fmaf(e, hv.x, ax); ay = fmaf(e, hv.y, ay);
            az = fmaf(e, hv.z, az); aw = fmaf(e, hv.w, aw);
        }
        float inv = 1.f / (den + 1e-16f);
        o.x = fmaxf(fmaf(ax, inv, bv.x), 0.f);
        o.y = fmaxf(fmaf(ay, inv, bv.y), 0.f);
        o.z = fmaxf(fmaf(az, inv, bv.z), 0.f);
        o.w = fmaxf(fmaf(aw, inv, bv.w), 0.f);
    }
    *reinterpret_cast<float4*>(&g_hrelu[w * 128 + lane * 4]) = o;
}

// ---------------- layer 2 aggregation + fused pooling -------------------------
__global__ __launch_bounds__(256, 8)
void k_edge2(const float* __restrict__ b2, const int* __restrict__ batch) {
    int w = (blockIdx.x * blockDim.x + threadIdx.x) >> 5;
    if (w >= NN) return;
    int lane = threadIdx.x & 31;
    float2 bv = *reinterpret_cast<const float2*>(&b2[lane * 2]);
    int beg = g_off[w], end = g_off[w + 1];
    float o0, o1;
    if (beg == end) {
        o0 = bv.x; o1 = bv.y;
    } else {
        float adw = g_adst2[w];
        float ce = g_ce2v[0];
        float a0 = 0.f, a1 = 0.f, den = 0.f;
#pragma unroll 8
        for (int j = beg; j < end; j++) {
            int2 p = g_sep[j];
            int s = p.x;
            float v = g_asrc2[s] + adw + __int_as_float(p.y) * ce;
            v = v > 0.f ? v : 0.2f * v;
            float e = __expf(v);
            den += e;
            float2 hv = *reinterpret_cast<const float2*>(&g_h2[s * 64 + lane * 2]);
            a0 = fmaf(e, hv.x, a0);
            a1 = fmaf(e, hv.y, a1);
        }
        float inv = 1.f / (den + 1e-16f);
        o0 = fmaf(a0, inv, bv.x);
        o1 = fmaf(a1, inv, bv.y);
    }
    int g = batch[w];
    atomicAdd(&g_gsum[g * 64 + lane * 2], o0);
    atomicAdd(&g_gsum[g * 64 + lane * 2 + 1], o1);
    if (lane == 0) atomicAdd(&g_gcnt[g], 1.f);
}

__global__ void k_final(const float* __restrict__ Wp, const float* __restrict__ bp,
                        float* __restrict__ out) {
    int w = (blockIdx.x * blockDim.x + threadIdx.x) >> 5;
    if (w >= GG) return;
    int lane = threadIdx.x & 31;
    float s0 = g_gsum[w * 64 + lane];
    float s1 = g_gsum[w * 64 + 32 + lane];
    float v = s0 * Wp[lane] + s1 * Wp[32 + lane];
#pragma unroll
    for (int off = 16; off; off >>= 1) v += __shfl_xor_sync(0xffffffffu, v, off);
    float cnt = g_gcnt[w];
    if (lane == 0) out[w] = v / cnt + bp[0];
    // self-clean for next call
    g_gsum[w * 64 + lane] = 0.f;
    g_gsum[w * 64 + 32 + lane] = 0.f;
    if (lane == 0) g_gcnt[w] = 0.f;
}

// ---------------- launch ------------------------------------------------------
extern "C" void kernel_launch(void* const* d_in, const int* in_sizes, int n_in,
                              void* d_out, int out_size) {
    const float* x     = (const float*)d_in[0];
    const int*   eidx  = (const int*)d_in[1];
    const float* eattr = (const float*)d_in[2];
    const int*   batch = (const int*)d_in[3];
    const float* W1  = (const float*)d_in[4];
    const float* as1 = (const float*)d_in[5];
    const float* ad1 = (const float*)d_in[6];
    const float* We1 = (const float*)d_in[7];
    const float* ae1 = (const float*)d_in[8];
    const float* b1  = (const float*)d_in[9];
    const float* W2  = (const float*)d_in[10];
    const float* as2 = (const float*)d_in[11];
    const float* ad2 = (const float*)d_in[12];
    const float* We2 = (const float*)d_in[13];
    const float* ae2 = (const float*)d_in[14];
    const float* b2  = (const float*)d_in[15];
    const float* Wp  = (const float*)d_in[16];
    const float* bp  = (const float*)d_in[17];
    float* out = (float*)d_out;

    const int* src = eidx;
    const int* dst = eidx + EE;

    k_l1<<<GMB1 + HB1, 256>>>(x, W1, as1, ad1, dst, We1, ae1, We2, ae2);
    k_csr<<<SCB, 256>>>(src, dst, eattr);
    k_edge1<<<EDGEB, 256>>>(b1);
    k_l2<<<GMB2, 256>>>(W2, as2, ad2);
    k_edge2<<<EDGEB, 256>>>(b2, batch);
    k_final<<<2, 1024>>>(Wp, bp, out);

    (void)in_sizes; (void)n_in; (void)out_size;
}